// round 1
// baseline (speedup 1.0000x reference)
#include <cuda_runtime.h>

// x: (16, 256, 128, 128) fp32, c = comp*64 + c4 (comp outer)
// out: (16, 256, 64, 64) fp32
// For each (b, c4, h2, w2): amp2[p] = sum_comp x[b, comp*64+c4, 2h2+kh, 2w2+kw]^2,
// p = kh*2+kw; pick first argmax p; emit the 4 component values at p.

#define NB   16
#define NC4  64
#define HH   128
#define WW   128
#define H2   64
#define W2   64

__device__ __forceinline__ float pick4(const float4& t, const float4& bt, int idx) {
    float v = t.x;
    v = (idx == 1) ? t.y  : v;
    v = (idx == 2) ? bt.x : v;
    v = (idx == 3) ? bt.y : v;
    return v;
}

__global__ __launch_bounds__(256)
void qmap_kernel(const float* __restrict__ x, float* __restrict__ out) {
    int tid = blockIdx.x * blockDim.x + threadIdx.x;
    // total threads = 16 * 64 * 64 * 32 = 2,097,152
    int j   = tid & 31;           // w2-pair index: covers w2 = 2j, 2j+1; w base = 4j
    int h2  = (tid >> 5)  & 63;
    int c4i = (tid >> 11) & 63;
    int b   = tid >> 17;

    const size_t plane       = (size_t)HH * WW;          // 16384
    const size_t comp_stride = (size_t)NC4 * plane;      // 64*16384

    size_t base = (size_t)(b * 4) * comp_stride
                + (size_t)c4i * plane
                + (size_t)(2 * h2) * WW
                + (size_t)(4 * j);

    float4 r0[4], r1[4];
#pragma unroll
    for (int cm = 0; cm < 4; cm++) {
        const float* p = x + base + (size_t)cm * comp_stride;
        r0[cm] = *reinterpret_cast<const float4*>(p);
        r1[cm] = *reinterpret_cast<const float4*>(p + WW);
    }

    // amp^2 for pixel 0 (cands: r0.x, r0.y, r1.x, r1.y) and pixel 1 (r0.z, r0.w, r1.z, r1.w)
    float a00 = 0.f, a01 = 0.f, a02 = 0.f, a03 = 0.f;
    float a10 = 0.f, a11 = 0.f, a12 = 0.f, a13 = 0.f;
#pragma unroll
    for (int cm = 0; cm < 4; cm++) {
        a00 = fmaf(r0[cm].x, r0[cm].x, a00);
        a01 = fmaf(r0[cm].y, r0[cm].y, a01);
        a02 = fmaf(r1[cm].x, r1[cm].x, a02);
        a03 = fmaf(r1[cm].y, r1[cm].y, a03);
        a10 = fmaf(r0[cm].z, r0[cm].z, a10);
        a11 = fmaf(r0[cm].w, r0[cm].w, a11);
        a12 = fmaf(r1[cm].z, r1[cm].z, a12);
        a13 = fmaf(r1[cm].w, r1[cm].w, a13);
    }

    // first-argmax (strict >)
    int i0 = 0; float b0 = a00;
    if (a01 > b0) { b0 = a01; i0 = 1; }
    if (a02 > b0) { b0 = a02; i0 = 2; }
    if (a03 > b0) { b0 = a03; i0 = 3; }
    int i1 = 0; float b1 = a10;
    if (a11 > b1) { b1 = a11; i1 = 1; }
    if (a12 > b1) { b1 = a12; i1 = 2; }
    if (a13 > b1) { b1 = a13; i1 = 3; }

    const size_t oplane       = (size_t)H2 * W2;         // 4096
    const size_t ocomp_stride = (size_t)NC4 * oplane;    // 64*4096
    size_t obase = (size_t)(b * 4) * ocomp_stride
                 + (size_t)c4i * oplane
                 + (size_t)h2 * W2
                 + (size_t)(2 * j);

#pragma unroll
    for (int cm = 0; cm < 4; cm++) {
        float v0 = pick4(r0[cm], r1[cm], i0);
        // pixel 1 uses .z/.w halves
        float4 t  = make_float4(r0[cm].z, r0[cm].w, 0.f, 0.f);
        float4 bt = make_float4(r1[cm].z, r1[cm].w, 0.f, 0.f);
        float v1 = pick4(t, bt, i1);
        float2 o = make_float2(v0, v1);
        *reinterpret_cast<float2*>(out + obase + (size_t)cm * ocomp_stride) = o;
    }
}

extern "C" void kernel_launch(void* const* d_in, const int* in_sizes, int n_in,
                              void* d_out, int out_size) {
    const float* x = (const float*)d_in[0];
    float* out = (float*)d_out;
    const int total = NB * NC4 * H2 * (W2 / 2);   // 2,097,152 threads
    const int block = 256;
    const int grid  = total / block;              // 8192
    qmap_kernel<<<grid, block>>>(x, out);
}